// round 2
// baseline (speedup 1.0000x reference)
#include <cuda_runtime.h>

// Problem constants (fixed by the dataset).
#define N_NEURONS 2000000
#define N_EDGES   16000000

// Shared-memory hash table for the active set (expected <= ~750 entries).
#define HBITS 12
#define HSIZE (1 << HBITS)          // 4096 slots
#define HMASK (HSIZE - 1)
#define MAX_LIST 2048               // fallback to direct gather beyond this
#define EMPTY_KEY 0xFFFFFFFFu

// Scratch state (allocation-free: __device__ globals).
__device__ float    g_x[N_NEURONS];     // neuron values
__device__ float    g_out[N_NEURONS];   // per-layer aggregation buffer
__device__ unsigned g_list_idx[MAX_LIST];
__device__ float    g_list_val[MAX_LIST];
__device__ unsigned g_cnt[4];           // active-list counters per compaction round

__device__ __forceinline__ unsigned hash_fn(unsigned k) {
    return (k * 2654435761u) >> (32 - HBITS);
}

// ---------------------------------------------------------------------------
// Init: x = e0, out = 0, counters = 0. Runs at the start of every launch so
// graph replays are self-contained and deterministic.
// ---------------------------------------------------------------------------
__global__ void k_init() {
    int stride = gridDim.x * blockDim.x;
    const int NV = N_NEURONS / 4;   // 2M divisible by 4
    float4* x4 = reinterpret_cast<float4*>(g_x);
    float4* o4 = reinterpret_cast<float4*>(g_out);
    const float4 z = make_float4(0.f, 0.f, 0.f, 0.f);
    for (int i = blockIdx.x * blockDim.x + threadIdx.x; i < NV; i += stride) {
        x4[i] = (i == 0) ? make_float4(1.f, 0.f, 0.f, 0.f) : z;
        o4[i] = z;
    }
    if (blockIdx.x == 0 && threadIdx.x < 4) g_cnt[threadIdx.x] = 0u;
}

// ---------------------------------------------------------------------------
// Layer 0 edge scan: active set is exactly {neuron 0, value 1.0}.
// Membership test is a compare against 0 — only src is streamed.
// ---------------------------------------------------------------------------
__global__ void k_edge_first(const int* __restrict__ src, const int* __restrict__ dst,
                             const int* __restrict__ widx, const float* __restrict__ weights) {
    long stride = (long)gridDim.x * blockDim.x * 4;
    for (long i = ((long)blockIdx.x * blockDim.x + threadIdx.x) * 4; i < N_EDGES; i += stride) {
        int4 s4 = *reinterpret_cast<const int4*>(src + i);
        int s[4] = {s4.x, s4.y, s4.z, s4.w};
        #pragma unroll
        for (int j = 0; j < 4; ++j) {
            if (s[j] == 0) {
                long e = i + j;
                atomicAdd(&g_out[__ldg(dst + e)], __ldg(weights + __ldg(widx + e)));
            }
        }
    }
}

// ---------------------------------------------------------------------------
// Layers 1,2 edge scan: membership via per-CTA shared-memory hash of the
// compacted active list. Falls back to direct g_x gather if the list
// overflowed (keeps correctness for any input). Probe loops are bounded so a
// corrupt table can never hang a CTA.
// ---------------------------------------------------------------------------
__global__ void k_edge_hash(const int* __restrict__ src, const int* __restrict__ dst,
                            const int* __restrict__ widx, const float* __restrict__ weights,
                            int layer, int round) {
    __shared__ unsigned sk[HSIZE];
    __shared__ float    sv[HSIZE];

    unsigned cnt = g_cnt[round];
    bool fallback = (cnt > MAX_LIST);

    if (!fallback) {
        for (int t = threadIdx.x; t < HSIZE; t += blockDim.x) sk[t] = EMPTY_KEY;
        __syncthreads();
        for (int t = threadIdx.x; t < (int)cnt; t += blockDim.x) {
            unsigned key = g_list_idx[t];
            float    val = g_list_val[t];
            unsigned h = hash_fn(key);
            int guard = 0;
            while (atomicCAS(&sk[h], EMPTY_KEY, key) != EMPTY_KEY && ++guard < HSIZE)
                h = (h + 1) & HMASK;
            sv[h] = val;
        }
        __syncthreads();
    }

    const int* s_ptr = src + (long)layer * N_EDGES;
    long base = (long)layer * N_EDGES;
    long stride = (long)gridDim.x * blockDim.x * 4;

    for (long i = ((long)blockIdx.x * blockDim.x + threadIdx.x) * 4; i < N_EDGES; i += stride) {
        int4 s4 = *reinterpret_cast<const int4*>(s_ptr + i);
        int s[4] = {s4.x, s4.y, s4.z, s4.w};
        #pragma unroll
        for (int j = 0; j < 4; ++j) {
            unsigned sj = (unsigned)s[j];
            float xv = 0.0f;
            if (fallback) {
                xv = g_x[sj];
            } else {
                unsigned h = hash_fn(sj);
                #pragma unroll 1
                for (int p = 0; p < HSIZE; ++p) {
                    unsigned k = sk[h];
                    if (k == EMPTY_KEY) break;
                    if (k == sj) { xv = sv[h]; break; }
                    h = (h + 1) & HMASK;
                }
            }
            if (xv != 0.0f) {
                long e = base + i + j;
                atomicAdd(&g_out[__ldg(dst + e)], xv * __ldg(weights + __ldg(widx + e)));
            }
        }
    }
}

// ---------------------------------------------------------------------------
// Update: x += relu(out); out -> 0 (write only where touched); optionally
// compact nonzero x into the global active list for the next layer's hash.
// ---------------------------------------------------------------------------
__global__ void k_update(int round, int do_compact) {
    int stride = gridDim.x * blockDim.x;
    for (int i = blockIdx.x * blockDim.x + threadIdx.x; i < N_NEURONS; i += stride) {
        float v = g_out[i];
        if (do_compact) {
            float xv = g_x[i];
            if (v != 0.0f) {
                g_out[i] = 0.0f;
                if (v > 0.0f) { xv += v; g_x[i] = xv; }
            }
            if (xv != 0.0f) {
                unsigned p = atomicAdd(&g_cnt[round], 1u);
                if (p < MAX_LIST) { g_list_idx[p] = (unsigned)i; g_list_val[p] = xv; }
            }
        } else {
            if (v != 0.0f) {
                g_out[i] = 0.0f;
                if (v > 0.0f) g_x[i] += v;
            }
        }
    }
}

// ---------------------------------------------------------------------------
// Layer 3 edge scan: only out[0] matters for the result, so scan dst == 0 and
// accumulate x[src]*w into g_out[0]. Gathers happen only for ~E/N hits.
// ---------------------------------------------------------------------------
__global__ void k_edge_last(const int* __restrict__ src, const int* __restrict__ dst,
                            const int* __restrict__ widx, const float* __restrict__ weights) {
    const long base = 3L * N_EDGES;
    const int* d_ptr = dst + base;
    long stride = (long)gridDim.x * blockDim.x * 4;
    for (long i = ((long)blockIdx.x * blockDim.x + threadIdx.x) * 4; i < N_EDGES; i += stride) {
        int4 d4 = *reinterpret_cast<const int4*>(d_ptr + i);
        int d[4] = {d4.x, d4.y, d4.z, d4.w};
        #pragma unroll
        for (int j = 0; j < 4; ++j) {
            if (d[j] == 0) {
                long e = base + i + j;
                atomicAdd(&g_out[0], g_x[__ldg(src + e)] * __ldg(weights + __ldg(widx + e)));
            }
        }
    }
}

__global__ void k_final(float* __restrict__ out) {
    out[0] = g_x[0] + fmaxf(g_out[0], 0.0f);
}

// ---------------------------------------------------------------------------
// Launch sequence (graph-capturable: kernel launches only).
// Inputs per metadata: [0]=weights f32[1024], [1]=src i32[4*16M],
// [2]=dst i32[4*16M], [3]=widx i32[4*16M]. Output: f32[1].
// ---------------------------------------------------------------------------
extern "C" void kernel_launch(void* const* d_in, const int* in_sizes, int n_in,
                              void* d_out, int out_size) {
    const float* weights = (const float*)d_in[0];
    const int*   src     = (const int*)d_in[1];
    const int*   dst     = (const int*)d_in[2];
    const int*   widx    = (const int*)d_in[3];
    float*       out     = (float*)d_out;

    const int EB = 1184, ET = 256;   // edge-scan grid (~8 blocks/SM)
    const int UB = 2048, UT = 256;   // neuron-update grid

    k_init<<<UB, UT>>>();
    k_edge_first<<<EB, ET>>>(src, dst, widx, weights);
    k_update<<<UB, UT>>>(0, 1);                          // compact -> round 0 list
    k_edge_hash<<<EB, ET>>>(src, dst, widx, weights, 1, 0);
    k_update<<<UB, UT>>>(1, 1);                          // compact -> round 1 list
    k_edge_hash<<<EB, ET>>>(src, dst, widx, weights, 2, 1);
    k_update<<<UB, UT>>>(2, 0);                          // apply relu only
    k_edge_last<<<EB, ET>>>(src, dst, widx, weights);
    k_final<<<1, 1>>>(out);
}

// round 3
// speedup vs baseline: 1.3893x; 1.3893x over previous
#include <cuda_runtime.h>

// Problem constants (fixed by the dataset).
#define N_NEURONS 2000000
#define N_EDGES   16000000

// Shared-memory hash table for the active set (expected <= ~100 entries).
#define HBITS 11
#define HSIZE (1 << HBITS)          // 2048 slots, 16KB smem total
#define HMASK (HSIZE - 1)
#define EMPTY_KEY 0xFFFFFFFFu

#define TCAP (1 << 20)              // touched-list capacity (fallback beyond)
#define ACAP (1 << 20)              // active-list capacity

// Scratch state (allocation-free: __device__ globals, zero-initialized at load;
// every launch leaves them pristine again => deterministic graph replays).
__device__ float    g_x[N_NEURONS];      // neuron values (all-zero between launches)
__device__ float    g_out[N_NEURONS];    // aggregation buffer (all-zero between launches)
__device__ unsigned g_act[ACAP];         // active neuron indices (monotone append)
__device__ unsigned g_acnt;
__device__ unsigned g_touched[TCAP];     // cells touched by current layer's scatter
__device__ unsigned g_tcnt[3];

__device__ __forceinline__ unsigned hash_fn(unsigned k) {
    return (k * 2654435761u) >> (32 - HBITS);
}

// Scatter with touched-list registration. val != 0 is guaranteed by callers,
// so exactly one adder per cell observes old == 0.0f.
__device__ __forceinline__ void scatter_edge(int d, float val, int r) {
    if (val == 0.0f) return;
    float old = atomicAdd(&g_out[d], val);
    if (old == 0.0f) {
        unsigned p = atomicAdd(&g_tcnt[r], 1u);
        if (p < TCAP) g_touched[p] = (unsigned)d;
    }
}

// ---------------------------------------------------------------------------
// Start: seed x[0]=1, active list = {0}, counters = 0. Assumes g_x/g_out are
// all-zero (true at load and restored by k_cleanup each launch).
// ---------------------------------------------------------------------------
__global__ void k_start() {
    g_x[0] = 1.0f;
    g_act[0] = 0u;
    g_acnt = 1u;
    g_tcnt[0] = 0u; g_tcnt[1] = 0u; g_tcnt[2] = 0u;
    g_out[0] = 0.0f;   // belt-and-braces (cleanup also zeroes it)
}

// ---------------------------------------------------------------------------
// Layer 0 edge scan: active set is exactly {0, value 1.0} -> compare only.
// ---------------------------------------------------------------------------
__global__ void k_edge_first(const int* __restrict__ src, const int* __restrict__ dst,
                             const int* __restrict__ widx, const float* __restrict__ weights) {
    long stride = (long)gridDim.x * blockDim.x * 8;
    for (long i = ((long)blockIdx.x * blockDim.x + threadIdx.x) * 8; i < N_EDGES; i += stride) {
        int4 a = __ldcs(reinterpret_cast<const int4*>(src + i));
        int4 b = __ldcs(reinterpret_cast<const int4*>(src + i + 4));
        int s[8] = {a.x, a.y, a.z, a.w, b.x, b.y, b.z, b.w};
        #pragma unroll
        for (int j = 0; j < 8; ++j) {
            if (s[j] == 0) {
                long e = i + j;
                scatter_edge(__ldg(dst + e), __ldg(weights + __ldg(widx + e)), 0);
            }
        }
    }
}

// ---------------------------------------------------------------------------
// Layers 1,2 edge scan: shared-memory hash of (active idx -> x value).
// Fast path = 1 LDS + compare (slot empty or exact hit); linear probe only on
// a foreign-key collision. Fallback to direct g_x gather if active set too big.
// ---------------------------------------------------------------------------
__global__ void k_edge_hash(const int* __restrict__ src, const int* __restrict__ dst,
                            const int* __restrict__ widx, const float* __restrict__ weights,
                            int layer, int round) {
    __shared__ unsigned sk[HSIZE];
    __shared__ float    sv[HSIZE];

    unsigned cnt = g_acnt;
    bool fallback = (cnt > (HSIZE / 2)) || (cnt > ACAP);

    if (!fallback) {
        for (int t = threadIdx.x; t < HSIZE; t += blockDim.x) sk[t] = EMPTY_KEY;
        __syncthreads();
        for (int t = threadIdx.x; t < (int)cnt; t += blockDim.x) {
            unsigned key = g_act[t];
            float    val = g_x[key];
            unsigned h = hash_fn(key);
            int guard = 0;
            while (atomicCAS(&sk[h], EMPTY_KEY, key) != EMPTY_KEY && sk[h] != key &&
                   ++guard < HSIZE)
                h = (h + 1) & HMASK;
            sv[h] = val;
        }
        __syncthreads();
    }

    const int* s_ptr = src + (long)layer * N_EDGES;
    long base = (long)layer * N_EDGES;
    long stride = (long)gridDim.x * blockDim.x * 8;

    for (long i = ((long)blockIdx.x * blockDim.x + threadIdx.x) * 8; i < N_EDGES; i += stride) {
        int4 a = __ldcs(reinterpret_cast<const int4*>(s_ptr + i));
        int4 b = __ldcs(reinterpret_cast<const int4*>(s_ptr + i + 4));
        int s[8] = {a.x, a.y, a.z, a.w, b.x, b.y, b.z, b.w};
        #pragma unroll
        for (int j = 0; j < 8; ++j) {
            unsigned sj = (unsigned)s[j];
            float xv = 0.0f;
            if (fallback) {
                xv = g_x[sj];
            } else {
                unsigned h = hash_fn(sj);
                unsigned k = sk[h];
                if (k == sj) {
                    xv = sv[h];
                } else if (k != EMPTY_KEY) {
                    #pragma unroll 1
                    for (int p = 0; p < HSIZE; ++p) {
                        h = (h + 1) & HMASK;
                        k = sk[h];
                        if (k == EMPTY_KEY) break;
                        if (k == sj) { xv = sv[h]; break; }
                    }
                }
            }
            if (xv != 0.0f) {
                long e = base + i + j;
                scatter_edge(__ldg(dst + e), xv * __ldg(weights + __ldg(widx + e)), round);
            }
        }
    }
}

// ---------------------------------------------------------------------------
// Update via touched list: x += relu(out), out -> 0, newly-active appended to
// active list. Full N sweep only if the touched list overflowed.
// ---------------------------------------------------------------------------
__global__ void k_update(int r) {
    unsigned tc = g_tcnt[r];
    int stride = gridDim.x * blockDim.x;
    int t0 = blockIdx.x * blockDim.x + threadIdx.x;
    if (tc <= TCAP) {
        for (unsigned t = t0; t < tc; t += stride) {
            unsigned i = g_touched[t];
            float v = g_out[i];
            g_out[i] = 0.0f;
            if (v > 0.0f) {
                float xo = g_x[i];
                g_x[i] = xo + v;
                if (xo == 0.0f) {
                    unsigned p = atomicAdd(&g_acnt, 1u);
                    if (p < ACAP) g_act[p] = i;
                }
            }
        }
    } else {
        for (int i = t0; i < N_NEURONS; i += stride) {
            float v = g_out[i];
            if (v != 0.0f) {
                g_out[i] = 0.0f;
                if (v > 0.0f) {
                    float xo = g_x[i];
                    g_x[i] = xo + v;
                    if (xo == 0.0f) {
                        unsigned p = atomicAdd(&g_acnt, 1u);
                        if (p < ACAP) g_act[p] = i;
                    }
                }
            }
        }
    }
}

// ---------------------------------------------------------------------------
// Layer 3 edge scan: only out[0] matters -> scan dst==0, gather x[src] on hits.
// ---------------------------------------------------------------------------
__global__ void k_edge_last(const int* __restrict__ src, const int* __restrict__ dst,
                            const int* __restrict__ widx, const float* __restrict__ weights) {
    const long base = 3L * N_EDGES;
    const int* d_ptr = dst + base;
    long stride = (long)gridDim.x * blockDim.x * 8;
    for (long i = ((long)blockIdx.x * blockDim.x + threadIdx.x) * 8; i < N_EDGES; i += stride) {
        int4 a = __ldcs(reinterpret_cast<const int4*>(d_ptr + i));
        int4 b = __ldcs(reinterpret_cast<const int4*>(d_ptr + i + 4));
        int d[8] = {a.x, a.y, a.z, a.w, b.x, b.y, b.z, b.w};
        #pragma unroll
        for (int j = 0; j < 8; ++j) {
            if (d[j] == 0) {
                long e = base + i + j;
                atomicAdd(&g_out[0], g_x[__ldg(src + e)] * __ldg(weights + __ldg(widx + e)));
            }
        }
    }
}

__global__ void k_final(float* __restrict__ out) {
    out[0] = g_x[0] + fmaxf(g_out[0], 0.0f);
}

// ---------------------------------------------------------------------------
// Cleanup: restore pristine all-zero state for the next replay. Walks the
// active list (full sweep only if it overflowed). Counters reset by k_start.
// ---------------------------------------------------------------------------
__global__ void k_cleanup() {
    unsigned ac = g_acnt;
    int stride = gridDim.x * blockDim.x;
    int t0 = blockIdx.x * blockDim.x + threadIdx.x;
    if (ac <= ACAP) {
        for (unsigned t = t0; t < ac; t += stride) g_x[g_act[t]] = 0.0f;
    } else {
        for (int i = t0; i < N_NEURONS; i += stride) g_x[i] = 0.0f;
    }
    if (t0 == 0) g_out[0] = 0.0f;
}

// ---------------------------------------------------------------------------
// Launch sequence (graph-capturable: kernel launches only).
// Inputs: [0]=weights f32[1024], [1]=src i32[4*16M], [2]=dst i32[4*16M],
// [3]=widx i32[4*16M]. Output: f32[1].
// ---------------------------------------------------------------------------
extern "C" void kernel_launch(void* const* d_in, const int* in_sizes, int n_in,
                              void* d_out, int out_size) {
    const float* weights = (const float*)d_in[0];
    const int*   src     = (const int*)d_in[1];
    const int*   dst     = (const int*)d_in[2];
    const int*   widx    = (const int*)d_in[3];
    float*       out     = (float*)d_out;

    const int EB = 1184, ET = 256;   // edge-scan grid (8 CTAs/SM)
    const int UB = 256,  UT = 256;   // bookkeeping grid (grid-stride, fallback-capable)

    k_start<<<1, 1>>>();
    k_edge_first<<<EB, ET>>>(src, dst, widx, weights);
    k_update<<<UB, UT>>>(0);
    k_edge_hash<<<EB, ET>>>(src, dst, widx, weights, 1, 1);
    k_update<<<UB, UT>>>(1);
    k_edge_hash<<<EB, ET>>>(src, dst, widx, weights, 2, 2);
    k_update<<<UB, UT>>>(2);
    k_edge_last<<<EB, ET>>>(src, dst, widx, weights);
    k_final<<<1, 1>>>(out);
    k_cleanup<<<UB, UT>>>();
}